// round 1
// baseline (speedup 1.0000x reference)
#include <cuda_runtime.h>
#include <math.h>

// Problem constants
#define BB   2
#define SS   2048
#define HID  2048
#define NH   16
#define HD   128
#define MROWS (BB*SS)   // 4096

// ---------------------------------------------------------------------------
// Scratch (device globals; no allocation allowed)
// ---------------------------------------------------------------------------
__device__ float g_q[MROWS * HID];     // Q projections  [B*S, HID]
__device__ float g_k[MROWS * HD];      // K projections  [B*S, HD]
__device__ float g_v[MROWS * HD];      // V projections  [B*S, HD]
__device__ float g_attn[MROWS * HID];  // attention out  [B*S, HID]

// ---------------------------------------------------------------------------
// SGEMM:  C[M,N] = A[M,K] @ B[K,N] + bias[N]
// 128x128 block tile, BK=8, 256 threads, 8x8 per-thread register tile.
// Requires M%128==0, N%128==0, K%8==0 (true for all our shapes).
// ---------------------------------------------------------------------------
__global__ __launch_bounds__(256) void sgemm_bias_kernel(
    const float* __restrict__ A, const float* __restrict__ Bm,
    const float* __restrict__ bias, float* __restrict__ C,
    int Md, int Nd, int Kd)
{
    __shared__ float As[8][128];   // transposed A tile: As[k][m]
    __shared__ float Bs[8][128];   // Bs[k][n]

    const int tid  = threadIdx.x;
    const int row0 = blockIdx.y * 128;
    const int col0 = blockIdx.x * 128;

    const int arow = tid >> 1;            // 0..127
    const int acol = (tid & 1) << 2;      // 0 or 4
    const int brow = tid >> 5;            // 0..7
    const int bcol = (tid & 31) << 2;     // 0..124

    const int ty = tid >> 4;              // 0..15
    const int tx = tid & 15;              // 0..15

    const float* Aptr = A + (size_t)(row0 + arow) * Kd + acol;
    const float* Bptr = Bm + (size_t)brow * Nd + col0 + bcol;

    float acc[8][8];
#pragma unroll
    for (int i = 0; i < 8; i++)
#pragma unroll
        for (int j = 0; j < 8; j++) acc[i][j] = 0.f;

    for (int k0 = 0; k0 < Kd; k0 += 8) {
        float4 a4 = *(const float4*)(Aptr + k0);
        float4 b4 = *(const float4*)(Bptr + (size_t)k0 * Nd);

        As[acol + 0][arow] = a4.x;
        As[acol + 1][arow] = a4.y;
        As[acol + 2][arow] = a4.z;
        As[acol + 3][arow] = a4.w;
        *(float4*)&Bs[brow][bcol] = b4;
        __syncthreads();

#pragma unroll
        for (int kk = 0; kk < 8; kk++) {
            float ar[8], br[8];
#pragma unroll
            for (int i = 0; i < 8; i++) ar[i] = As[kk][ty * 8 + i];
#pragma unroll
            for (int j = 0; j < 8; j++) br[j] = Bs[kk][tx * 8 + j];
#pragma unroll
            for (int i = 0; i < 8; i++)
#pragma unroll
                for (int j = 0; j < 8; j++)
                    acc[i][j] += ar[i] * br[j];
        }
        __syncthreads();
    }

    float bv[8];
#pragma unroll
    for (int j = 0; j < 8; j++) bv[j] = bias[col0 + tx * 8 + j];

#pragma unroll
    for (int i = 0; i < 8; i++) {
        const int row = row0 + ty * 8 + i;
        float* cp = C + (size_t)row * Nd + col0 + tx * 8;
        float4 o0 = make_float4(acc[i][0] + bv[0], acc[i][1] + bv[1],
                                acc[i][2] + bv[2], acc[i][3] + bv[3]);
        float4 o1 = make_float4(acc[i][4] + bv[4], acc[i][5] + bv[5],
                                acc[i][6] + bv[6], acc[i][7] + bv[7]);
        *(float4*)(cp)     = o0;
        *(float4*)(cp + 4) = o1;
    }
}

// ---------------------------------------------------------------------------
// Flash attention (MQA): per (batch, head) block processes 64 query rows.
// Online softmax, K/V tiles of 64, D=128 fully resident.
// 256 threads: 16x16 grid; each thread owns 4x4 score tile and 4x8 O tile.
// ---------------------------------------------------------------------------
#define FBM 64
#define FBN 64
#define QPITCH 132
#define PPITCH 68
#define FLASH_SMEM_FLOATS (3 * FBM * QPITCH + FBM * PPITCH)
#define FLASH_SMEM_BYTES  (FLASH_SMEM_FLOATS * 4)

__global__ __launch_bounds__(256) void mqa_flash_kernel(
    const float* __restrict__ q, const float* __restrict__ kmat,
    const float* __restrict__ vmat, float* __restrict__ o)
{
    extern __shared__ float sm[];
    float* smQ = sm;                       // [64][132]
    float* smK = smQ + FBM * QPITCH;       // [64][132]
    float* smV = smK + FBN * QPITCH;       // [64][132]
    float* smP = smV + FBN * QPITCH;       // [64][68]

    const int tid = threadIdx.x;
    const int ty  = tid >> 4;   // 0..15 -> query rows ty*4..+3
    const int tx  = tid & 15;   // 0..15 -> score cols tx*4..+3, O cols tx*8..+7
    const int m0  = blockIdx.x * FBM;
    const int h   = blockIdx.y;
    const int bb  = blockIdx.z;
    const float scale = 0.088388347648318447f;  // 1/sqrt(128)

    // ---- load Q tile (pre-scaled) ----
    const float* qbase = q + ((size_t)(bb * SS + m0)) * HID + h * HD;
#pragma unroll
    for (int it = 0; it < 8; it++) {
        int idx = tid + it * 256;         // float4 index 0..2047
        int r = idx >> 5;                 // 32 float4 per 128-float row
        int c = (idx & 31) << 2;
        float4 v4 = *(const float4*)(qbase + (size_t)r * HID + c);
        smQ[r * QPITCH + c + 0] = v4.x * scale;
        smQ[r * QPITCH + c + 1] = v4.y * scale;
        smQ[r * QPITCH + c + 2] = v4.z * scale;
        smQ[r * QPITCH + c + 3] = v4.w * scale;
    }

    float mrow[4], lrow[4], acc[4][8];
#pragma unroll
    for (int r = 0; r < 4; r++) {
        mrow[r] = -INFINITY; lrow[r] = 0.f;
#pragma unroll
        for (int d = 0; d < 8; d++) acc[r][d] = 0.f;
    }

    for (int n0 = 0; n0 < SS; n0 += FBN) {
        __syncthreads();   // prior PV done (and Q visible on first iter)

        const float* kbase = kmat + ((size_t)(bb * SS + n0)) * HD;
        const float* vbase = vmat + ((size_t)(bb * SS + n0)) * HD;
#pragma unroll
        for (int it = 0; it < 8; it++) {
            int idx = tid + it * 256;
            int r = idx >> 5;
            int c = (idx & 31) << 2;
            float4 k4 = *(const float4*)(kbase + (size_t)r * HD + c);
            float4 v4 = *(const float4*)(vbase + (size_t)r * HD + c);
            *(float4*)&smK[r * QPITCH + c] = k4;
            *(float4*)&smV[r * QPITCH + c] = v4;
        }
        __syncthreads();

        // ---- S = Q @ K^T (per-thread 4x4) ----
        float s[4][4];
#pragma unroll
        for (int r = 0; r < 4; r++)
#pragma unroll
            for (int c = 0; c < 4; c++) s[r][c] = 0.f;

#pragma unroll 8
        for (int kk = 0; kk < HD; kk += 2) {
            float2 qr[4], kr[4];
#pragma unroll
            for (int r = 0; r < 4; r++)
                qr[r] = *(const float2*)&smQ[(ty * 4 + r) * QPITCH + kk];
#pragma unroll
            for (int c = 0; c < 4; c++)
                kr[c] = *(const float2*)&smK[(tx * 4 + c) * QPITCH + kk];
#pragma unroll
            for (int r = 0; r < 4; r++)
#pragma unroll
                for (int c = 0; c < 4; c++)
                    s[r][c] += qr[r].x * kr[c].x + qr[r].y * kr[c].y;
        }

        // ---- online softmax update (row reductions over 16-lane groups) ----
#pragma unroll
        for (int r = 0; r < 4; r++) {
            float rm = fmaxf(fmaxf(s[r][0], s[r][1]), fmaxf(s[r][2], s[r][3]));
#pragma unroll
            for (int off = 8; off > 0; off >>= 1)
                rm = fmaxf(rm, __shfl_xor_sync(0xffffffffu, rm, off, 16));

            float mnew  = fmaxf(mrow[r], rm);
            float alpha = __expf(mrow[r] - mnew);

            float p0 = __expf(s[r][0] - mnew);
            float p1 = __expf(s[r][1] - mnew);
            float p2 = __expf(s[r][2] - mnew);
            float p3 = __expf(s[r][3] - mnew);
            float rs = p0 + p1 + p2 + p3;
#pragma unroll
            for (int off = 8; off > 0; off >>= 1)
                rs += __shfl_xor_sync(0xffffffffu, rs, off, 16);

            lrow[r] = lrow[r] * alpha + rs;
            mrow[r] = mnew;
#pragma unroll
            for (int d = 0; d < 8; d++) acc[r][d] *= alpha;

            float* pp = &smP[(ty * 4 + r) * PPITCH + tx * 4];
            pp[0] = p0; pp[1] = p1; pp[2] = p2; pp[3] = p3;
        }
        __syncthreads();

        // ---- O += P @ V ----
#pragma unroll 8
        for (int j = 0; j < FBN; j += 2) {
            float2 pr[4];
#pragma unroll
            for (int r = 0; r < 4; r++)
                pr[r] = *(const float2*)&smP[(ty * 4 + r) * PPITCH + j];
            float4 v0a = *(const float4*)&smV[j * QPITCH + tx * 8];
            float4 v0b = *(const float4*)&smV[j * QPITCH + tx * 8 + 4];
            float4 v1a = *(const float4*)&smV[(j + 1) * QPITCH + tx * 8];
            float4 v1b = *(const float4*)&smV[(j + 1) * QPITCH + tx * 8 + 4];
#pragma unroll
            for (int r = 0; r < 4; r++) {
                acc[r][0] += pr[r].x * v0a.x + pr[r].y * v1a.x;
                acc[r][1] += pr[r].x * v0a.y + pr[r].y * v1a.y;
                acc[r][2] += pr[r].x * v0a.z + pr[r].y * v1a.z;
                acc[r][3] += pr[r].x * v0a.w + pr[r].y * v1a.w;
                acc[r][4] += pr[r].x * v0b.x + pr[r].y * v1b.x;
                acc[r][5] += pr[r].x * v0b.y + pr[r].y * v1b.y;
                acc[r][6] += pr[r].x * v0b.z + pr[r].y * v1b.z;
                acc[r][7] += pr[r].x * v0b.w + pr[r].y * v1b.w;
            }
        }
    }

    // ---- normalize and write ----
    float* obase = o + ((size_t)(bb * SS + m0)) * HID + h * HD;
#pragma unroll
    for (int r = 0; r < 4; r++) {
        const float inv = 1.f / lrow[r];
        float* op = obase + (size_t)(ty * 4 + r) * HID + tx * 8;
        float4 o0 = make_float4(acc[r][0] * inv, acc[r][1] * inv,
                                acc[r][2] * inv, acc[r][3] * inv);
        float4 o1 = make_float4(acc[r][4] * inv, acc[r][5] * inv,
                                acc[r][6] * inv, acc[r][7] * inv);
        *(float4*)(op)     = o0;
        *(float4*)(op + 4) = o1;
    }
}

// ---------------------------------------------------------------------------
// Launch
// ---------------------------------------------------------------------------
extern "C" void kernel_launch(void* const* d_in, const int* in_sizes, int n_in,
                              void* d_out, int out_size)
{
    const float* X  = (const float*)d_in[0];
    const float* Wq = (const float*)d_in[1];
    const float* bq = (const float*)d_in[2];
    const float* Wk = (const float*)d_in[3];
    const float* bk = (const float*)d_in[4];
    const float* Wv = (const float*)d_in[5];
    const float* bv = (const float*)d_in[6];
    const float* Wo = (const float*)d_in[7];
    const float* bo = (const float*)d_in[8];
    float* out = (float*)d_out;

    float *pq, *pk, *pv, *pa;
    cudaGetSymbolAddress((void**)&pq, g_q);
    cudaGetSymbolAddress((void**)&pk, g_k);
    cudaGetSymbolAddress((void**)&pv, g_v);
    cudaGetSymbolAddress((void**)&pa, g_attn);

    cudaFuncSetAttribute(mqa_flash_kernel,
                         cudaFuncAttributeMaxDynamicSharedMemorySize,
                         FLASH_SMEM_BYTES);

    dim3 blk(256);

    // Q projection: [4096,2048] = X @ Wq + bq
    dim3 gq(HID / 128, MROWS / 128);
    sgemm_bias_kernel<<<gq, blk>>>(X, Wq, bq, pq, MROWS, HID, HID);

    // K / V projections: [4096,128]
    dim3 gkv(HD / 128, MROWS / 128);
    sgemm_bias_kernel<<<gkv, blk>>>(X, Wk, bk, pk, MROWS, HD, HID);
    sgemm_bias_kernel<<<gkv, blk>>>(X, Wv, bv, pv, MROWS, HD, HID);

    // Flash attention: grid (S/64, NH, B)
    dim3 gf(SS / FBM, NH, BB);
    mqa_flash_kernel<<<gf, blk, FLASH_SMEM_BYTES>>>(pq, pk, pv, pa);

    // Output projection: out = attn @ Wo + bo
    dim3 go(HID / 128, MROWS / 128);
    sgemm_bias_kernel<<<go, blk>>>(pa, Wo, bo, out, MROWS, HID, HID);
}

// round 4
// speedup vs baseline: 3.5657x; 3.5657x over previous
#include <cuda_runtime.h>
#include <cuda_bf16.h>
#include <cstdint>
#include <math.h>

// Problem constants
#define BB   2
#define SS   2048
#define HID  2048
#define NH   16
#define HD   128
#define MROWS (BB*SS)   // 4096

// ---------------------------------------------------------------------------
// Warp-MMA primitives (baseline PTX ISA — no 'a'-target features)
// ---------------------------------------------------------------------------
__device__ __forceinline__ uint32_t smem_u32(const void* p) {
    uint32_t a;
    asm("{ .reg .u64 t; cvta.to.shared.u64 t, %1; cvt.u32.u64 %0, t; }"
        : "=r"(a) : "l"(p));
    return a;
}

__device__ __forceinline__ void ldm_x4(uint32_t* r, uint32_t addr) {
    asm volatile("ldmatrix.sync.aligned.m8n8.x4.shared.b16 {%0,%1,%2,%3}, [%4];"
        : "=r"(r[0]), "=r"(r[1]), "=r"(r[2]), "=r"(r[3]) : "r"(addr));
}
__device__ __forceinline__ void ldm_x4t(uint32_t* r, uint32_t addr) {
    asm volatile("ldmatrix.sync.aligned.m8n8.x4.trans.shared.b16 {%0,%1,%2,%3}, [%4];"
        : "=r"(r[0]), "=r"(r[1]), "=r"(r[2]), "=r"(r[3]) : "r"(addr));
}
__device__ __forceinline__ void mma_bf16(float* d, const uint32_t* a, const uint32_t* b) {
    asm volatile(
        "mma.sync.aligned.m16n8k16.row.col.f32.bf16.bf16.f32 "
        "{%0,%1,%2,%3}, {%4,%5,%6,%7}, {%8,%9}, {%0,%1,%2,%3};"
        : "+f"(d[0]), "+f"(d[1]), "+f"(d[2]), "+f"(d[3])
        : "r"(a[0]), "r"(a[1]), "r"(a[2]), "r"(a[3]), "r"(b[0]), "r"(b[1]));
}
__device__ __forceinline__ void cp16(uint32_t saddr, const void* g) {
    asm volatile("cp.async.cg.shared.global [%0], [%1], 16;"
        :: "r"(saddr), "l"(g));
}
#define CP_COMMIT() asm volatile("cp.async.commit_group;")
#define CP_WAIT(n)  asm volatile("cp.async.wait_group %0;" :: "n"(n))

// ---------------------------------------------------------------------------
// Scratch (device globals; no allocation allowed)
// ---------------------------------------------------------------------------
__device__ __nv_bfloat16 g_xhi[MROWS * HID], g_xlo[MROWS * HID];
__device__ __nv_bfloat16 g_qhi[MROWS * HID], g_qlo[MROWS * HID];
__device__ __nv_bfloat16 g_khi[MROWS * HD],  g_klo[MROWS * HD];
__device__ __nv_bfloat16 g_vhi[MROWS * HD],  g_vlo[MROWS * HD];
__device__ __nv_bfloat16 g_ahi[MROWS * HID], g_alo[MROWS * HID];
__device__ __nv_bfloat16 g_wqh[HID * HID], g_wql[HID * HID];
__device__ __nv_bfloat16 g_woh[HID * HID], g_wol[HID * HID];
__device__ __nv_bfloat16 g_wkh[HID * HD],  g_wkl[HID * HD];
__device__ __nv_bfloat16 g_wvh[HID * HD],  g_wvl[HID * HD];

// ---------------------------------------------------------------------------
// Split fp32 -> bf16 hi + lo
// ---------------------------------------------------------------------------
__global__ void split_kernel(const float* __restrict__ in,
                             __nv_bfloat16* __restrict__ hi,
                             __nv_bfloat16* __restrict__ lo, int n4)
{
    int i = blockIdx.x * blockDim.x + threadIdx.x;
    if (i >= n4) return;
    float4 v = ((const float4*)in)[i];
    __nv_bfloat16 h0 = __float2bfloat16(v.x), h1 = __float2bfloat16(v.y);
    __nv_bfloat16 h2 = __float2bfloat16(v.z), h3 = __float2bfloat16(v.w);
    __nv_bfloat16 l0 = __float2bfloat16(v.x - __bfloat162float(h0));
    __nv_bfloat16 l1 = __float2bfloat16(v.y - __bfloat162float(h1));
    __nv_bfloat16 l2 = __float2bfloat16(v.z - __bfloat162float(h2));
    __nv_bfloat16 l3 = __float2bfloat16(v.w - __bfloat162float(h3));
    ((__nv_bfloat162*)hi)[2 * i + 0] = __nv_bfloat162(h0, h1);
    ((__nv_bfloat162*)hi)[2 * i + 1] = __nv_bfloat162(h2, h3);
    ((__nv_bfloat162*)lo)[2 * i + 0] = __nv_bfloat162(l0, l1);
    ((__nv_bfloat162*)lo)[2 * i + 1] = __nv_bfloat162(l2, l3);
}

// ---------------------------------------------------------------------------
// Projection GEMM: C[M,N] = A[M,2048] @ B[2048,N] + bias, hi/lo split inputs.
// Block 128x128, BK=32, 8 warps (2x4), warp tile 64x32.
// A smem pitch 80 B (32 bf16 + pad); B smem pitch 272 B (128 bf16 + pad).
// Output: either f32 C, or bf16 hi/lo pair (for chaining).
// ---------------------------------------------------------------------------
#define PA_PITCH 80
#define PB_PITCH 272
#define PA_TILE  (128 * PA_PITCH)              // 10240
#define PB_TILE  (32 * PB_PITCH)               // 8704
#define PSTAGE   (2 * PA_TILE + 2 * PB_TILE)   // 37888
#define PROJ_SMEM (2 * PSTAGE)                 // 75776
#define NKC 64                                 // 2048/32

__global__ __launch_bounds__(256, 1) void gemm_mma_kernel(
    const __nv_bfloat16* __restrict__ Ahi, const __nv_bfloat16* __restrict__ Alo,
    const __nv_bfloat16* __restrict__ Bhi, const __nv_bfloat16* __restrict__ Blo,
    const float* __restrict__ bias,
    float* __restrict__ Cf, __nv_bfloat16* __restrict__ Chi,
    __nv_bfloat16* __restrict__ Clo, int Nd)
{
    extern __shared__ char smx[];
    const uint32_t sb = smem_u32(smx);
    const int tid  = threadIdx.x;
    const int lane = tid & 31;
    const int wid  = tid >> 5;
    const int wm   = wid >> 2;          // 0..1
    const int wn   = wid & 3;           // 0..3
    const int n0   = blockIdx.x << 7;
    const int m0   = blockIdx.y << 7;

    const __nv_bfloat16* gA_h = Ahi + ((size_t)m0 << 11);
    const __nv_bfloat16* gA_l = Alo + ((size_t)m0 << 11);

    float acc[4][4][4];
#pragma unroll
    for (int i = 0; i < 4; i++)
#pragma unroll
        for (int j = 0; j < 4; j++)
#pragma unroll
            for (int k = 0; k < 4; k++) acc[i][j][k] = 0.f;

    // ---- async tile loaders ----
    auto loadA = [&](uint32_t s, const __nv_bfloat16* g) {
#pragma unroll
        for (int i = 0; i < 2; i++) {
            int q = tid + (i << 8);
            int r = q >> 2, c = q & 3;
            cp16(s + r * PA_PITCH + c * 16, g + (size_t)r * 2048 + c * 8);
        }
    };
    auto loadB = [&](uint32_t s, const __nv_bfloat16* g) {
#pragma unroll
        for (int i = 0; i < 2; i++) {
            int q = tid + (i << 8);
            int r = q >> 4, c = q & 15;
            cp16(s + r * PB_PITCH + c * 16, g + (size_t)r * Nd + c * 8);
        }
    };
    auto loadStage = [&](int buf, int ks) {
        uint32_t s = sb + buf * PSTAGE;
        loadA(s,                        gA_h + (size_t)ks * 32);
        loadA(s + PA_TILE,              gA_l + (size_t)ks * 32);
        loadB(s + 2 * PA_TILE,          Bhi + (size_t)ks * 32 * Nd + n0);
        loadB(s + 2 * PA_TILE + PB_TILE, Blo + (size_t)ks * 32 * Nd + n0);
    };

    loadStage(0, 0);
    CP_COMMIT();

    for (int ks = 0; ks < NKC; ks++) {
        if (ks + 1 < NKC) { loadStage((ks + 1) & 1, ks + 1); CP_COMMIT(); CP_WAIT(1); }
        else              { CP_WAIT(0); }
        __syncthreads();

        const uint32_t st = sb + (ks & 1) * PSTAGE;
        const uint32_t sAh = st, sAl = st + PA_TILE;
        const uint32_t sBh = st + 2 * PA_TILE, sBl = sBh + PB_TILE;

#pragma unroll
        for (int kk = 0; kk < 2; kk++) {
            uint32_t ah[4][4], al[4][4], bh[2][4], bl[2][4];
            const int arow_off = (lane & 15);
            const int akcol = kk * 16 + (lane >> 4) * 8;
#pragma unroll
            for (int mi = 0; mi < 4; mi++) {
                uint32_t ao = (uint32_t)((wm * 64 + mi * 16 + arow_off) * PA_PITCH + akcol * 2);
                ldm_x4(ah[mi], sAh + ao);
                ldm_x4(al[mi], sAl + ao);
            }
            const int bkrow = kk * 16 + (lane & 15);
#pragma unroll
            for (int nj = 0; nj < 2; nj++) {
                int ncol = wn * 32 + nj * 16 + (lane >> 4) * 8;
                uint32_t bo = (uint32_t)(bkrow * PB_PITCH + ncol * 2);
                ldm_x4t(bh[nj], sBh + bo);
                ldm_x4t(bl[nj], sBl + bo);
            }
#pragma unroll
            for (int mi = 0; mi < 4; mi++)
#pragma unroll
                for (int ni = 0; ni < 4; ni++) {
                    const uint32_t* ph = &bh[ni >> 1][(ni & 1) * 2];
                    const uint32_t* pl = &bl[ni >> 1][(ni & 1) * 2];
                    mma_bf16(acc[mi][ni], ah[mi], ph);
                    mma_bf16(acc[mi][ni], ah[mi], pl);
                    mma_bf16(acc[mi][ni], al[mi], ph);
                }
        }
        __syncthreads();
    }

    // ---- epilogue ----
#pragma unroll
    for (int mi = 0; mi < 4; mi++) {
        int rA = m0 + wm * 64 + mi * 16 + (lane >> 2);
        int rB = rA + 8;
#pragma unroll
        for (int ni = 0; ni < 4; ni++) {
            int col = n0 + wn * 32 + ni * 8 + (lane & 3) * 2;
            float b0 = bias[col], b1 = bias[col + 1];
            float v0 = acc[mi][ni][0] + b0, v1 = acc[mi][ni][1] + b1;
            float v2 = acc[mi][ni][2] + b0, v3 = acc[mi][ni][3] + b1;
            if (Cf) {
                *(float2*)(Cf + (size_t)rA * Nd + col) = make_float2(v0, v1);
                *(float2*)(Cf + (size_t)rB * Nd + col) = make_float2(v2, v3);
            } else {
                __nv_bfloat16 h0 = __float2bfloat16(v0), h1 = __float2bfloat16(v1);
                __nv_bfloat16 h2 = __float2bfloat16(v2), h3 = __float2bfloat16(v3);
                *(__nv_bfloat162*)(Chi + (size_t)rA * Nd + col) = __nv_bfloat162(h0, h1);
                *(__nv_bfloat162*)(Chi + (size_t)rB * Nd + col) = __nv_bfloat162(h2, h3);
                *(__nv_bfloat162*)(Clo + (size_t)rA * Nd + col) = __nv_bfloat162(
                    __float2bfloat16(v0 - __bfloat162float(h0)),
                    __float2bfloat16(v1 - __bfloat162float(h1)));
                *(__nv_bfloat162*)(Clo + (size_t)rB * Nd + col) = __nv_bfloat162(
                    __float2bfloat16(v2 - __bfloat162float(h2)),
                    __float2bfloat16(v3 - __bfloat162float(h3)));
            }
        }
    }
}

// ---------------------------------------------------------------------------
// Flash attention (MQA) on mma.sync: 64 q-rows per CTA, KV tiles of 64.
// smem pitches: Q/K/V 272 B; S 68 floats; P 144 B.
// ---------------------------------------------------------------------------
#define FQP 272
#define FPP 144
#define OFF_QH 0
#define OFF_QL 17408
#define OFF_KH 34816
#define OFF_KL 52224
#define OFF_VH 69632
#define OFF_VL 87040
#define OFF_S  104448
#define OFF_PH 121856
#define OFF_PL 131072
#define OFF_AL 140288
#define OFF_LL 140544
#define FLASH_SMEM 140800

__global__ __launch_bounds__(256, 1) void mqa_mma_kernel(
    const __nv_bfloat16* __restrict__ qhi, const __nv_bfloat16* __restrict__ qlo,
    const __nv_bfloat16* __restrict__ khi, const __nv_bfloat16* __restrict__ klo,
    const __nv_bfloat16* __restrict__ vhi, const __nv_bfloat16* __restrict__ vlo,
    __nv_bfloat16* __restrict__ ohi, __nv_bfloat16* __restrict__ olo)
{
    extern __shared__ char smx[];
    const uint32_t sb = smem_u32(smx);
    float* smS = (float*)(smx + OFF_S);
    float* smA = (float*)(smx + OFF_AL);
    float* smL = (float*)(smx + OFF_LL);

    const int tid  = threadIdx.x;
    const int lane = tid & 31;
    const int wid  = tid >> 5;
    const int wm   = wid >> 2;         // 0..1
    const int wn   = wid & 3;          // 0..3
    const int m0   = blockIdx.x * 64;
    const int h    = blockIdx.y;
    const int bb   = blockIdx.z;
    const float scale = 0.088388347648318447f;   // 1/sqrt(128)

    auto load64 = [&](uint32_t s, const __nv_bfloat16* g, int ld) {
#pragma unroll
        for (int i = 0; i < 4; i++) {
            int q = tid + (i << 8);
            int r = q >> 4, c = q & 15;
            cp16(s + r * FQP + c * 16, g + (size_t)r * ld + c * 8);
        }
    };

    // Q tiles (persist whole kernel)
    const size_t qbase = ((size_t)(bb * SS + m0)) * HID + h * HD;
    load64(sb + OFF_QH, qhi + qbase, HID);
    load64(sb + OFF_QL, qlo + qbase, HID);
    CP_COMMIT();

    // softmax state (row = tid>>2, 4 thread-copies per row)
    const int srow = tid >> 2;
    const int seg  = tid & 3;
    float mrun = -INFINITY, lrun = 0.f;

    float oacc[2][4][4];
#pragma unroll
    for (int i = 0; i < 2; i++)
#pragma unroll
        for (int j = 0; j < 4; j++)
#pragma unroll
            for (int k = 0; k < 4; k++) oacc[i][j][k] = 0.f;

    for (int t = 0; t < SS / 64; t++) {
        __syncthreads();   // prior PV done before overwriting K/V
        const size_t kvb = ((size_t)(bb * SS + t * 64)) * HD;
        load64(sb + OFF_KH, khi + kvb, HD);
        load64(sb + OFF_KL, klo + kvb, HD);
        load64(sb + OFF_VH, vhi + kvb, HD);
        load64(sb + OFF_VL, vlo + kvb, HD);
        CP_COMMIT();
        CP_WAIT(0);
        __syncthreads();

        // ---- S = Q @ K^T : warp tile 32(m) x 16(n), K-dim 128 ----
        float sacc[2][2][4];
#pragma unroll
        for (int i = 0; i < 2; i++)
#pragma unroll
            for (int j = 0; j < 2; j++)
#pragma unroll
                for (int k = 0; k < 4; k++) sacc[i][j][k] = 0.f;

#pragma unroll
        for (int kk = 0; kk < 8; kk++) {
            uint32_t ah[2][4], al[2][4], bh[4], bl[4];
            const int akcol = kk * 16 + (lane >> 4) * 8;
#pragma unroll
            for (int mi = 0; mi < 2; mi++) {
                uint32_t ao = (uint32_t)((wm * 32 + mi * 16 + (lane & 15)) * FQP + akcol * 2);
                ldm_x4(ah[mi], sb + OFF_QH + ao);
                ldm_x4(al[mi], sb + OFF_QL + ao);
            }
            {
                int keyrow = wn * 16 + (lane >> 4) * 8 + (lane & 7);
                int kcol   = kk * 16 + ((lane >> 3) & 1) * 8;
                uint32_t bo = (uint32_t)(keyrow * FQP + kcol * 2);
                ldm_x4(bh, sb + OFF_KH + bo);
                ldm_x4(bl, sb + OFF_KL + bo);
            }
#pragma unroll
            for (int mi = 0; mi < 2; mi++)
#pragma unroll
                for (int ni = 0; ni < 2; ni++) {
                    mma_bf16(sacc[mi][ni], ah[mi], &bh[ni * 2]);
                    mma_bf16(sacc[mi][ni], ah[mi], &bl[ni * 2]);
                    mma_bf16(sacc[mi][ni], al[mi], &bh[ni * 2]);
                }
        }
        // store S to smem
#pragma unroll
        for (int mi = 0; mi < 2; mi++)
#pragma unroll
            for (int ni = 0; ni < 2; ni++) {
                int r = wm * 32 + mi * 16 + (lane >> 2);
                int c = wn * 16 + ni * 8 + (lane & 3) * 2;
                *(float2*)&smS[r * 68 + c]       = make_float2(sacc[mi][ni][0], sacc[mi][ni][1]);
                *(float2*)&smS[(r + 8) * 68 + c] = make_float2(sacc[mi][ni][2], sacc[mi][ni][3]);
            }
        __syncthreads();

        // ---- online softmax: thread -> (row=tid>>2, 16 cols) ----
        {
            float sv[16];
#pragma unroll
            for (int j = 0; j < 16; j++)
                sv[j] = smS[srow * 68 + seg * 16 + j] * scale;
            float rm = sv[0];
#pragma unroll
            for (int j = 1; j < 16; j++) rm = fmaxf(rm, sv[j]);
            rm = fmaxf(rm, __shfl_xor_sync(0xffffffffu, rm, 1));
            rm = fmaxf(rm, __shfl_xor_sync(0xffffffffu, rm, 2));

            float mnew  = fmaxf(mrun, rm);
            float alpha = __expf(mrun - mnew);
            float rs = 0.f;
            uint32_t* ph = (uint32_t*)(smx + OFF_PH + srow * FPP + seg * 32);
            uint32_t* pl = (uint32_t*)(smx + OFF_PL + srow * FPP + seg * 32);
#pragma unroll
            for (int j = 0; j < 8; j++) {
                float p0 = __expf(sv[2 * j]     - mnew);
                float p1 = __expf(sv[2 * j + 1] - mnew);
                rs += p0 + p1;
                __nv_bfloat16 h0 = __float2bfloat16(p0), h1 = __float2bfloat16(p1);
                __nv_bfloat162 hh(h0, h1);
                __nv_bfloat162 ll(__float2bfloat16(p0 - __bfloat162float(h0)),
                                  __float2bfloat16(p1 - __bfloat162float(h1)));
                ph[j] = *(uint32_t*)&hh;
                pl[j] = *(uint32_t*)&ll;
            }
            rs += __shfl_xor_sync(0xffffffffu, rs, 1);
            rs += __shfl_xor_sync(0xffffffffu, rs, 2);
            lrun = lrun * alpha + rs;
            mrun = mnew;
            if (seg == 0) smA[srow] = alpha;
        }
        __syncthreads();

        // ---- O = O*alpha + P @ V : warp tile 32(m) x 32(d), K=64 keys ----
#pragma unroll
        for (int mi = 0; mi < 2; mi++) {
            float aA = smA[wm * 32 + mi * 16 + (lane >> 2)];
            float aB = smA[wm * 32 + mi * 16 + (lane >> 2) + 8];
#pragma unroll
            for (int ni = 0; ni < 4; ni++) {
                oacc[mi][ni][0] *= aA; oacc[mi][ni][1] *= aA;
                oacc[mi][ni][2] *= aB; oacc[mi][ni][3] *= aB;
            }
        }
#pragma unroll
        for (int kk = 0; kk < 4; kk++) {
            uint32_t ph[2][4], pl[2][4], vh[2][4], vl[2][4];
            const int akcol = kk * 16 + (lane >> 4) * 8;
#pragma unroll
            for (int mi = 0; mi < 2; mi++) {
                uint32_t ao = (uint32_t)((wm * 32 + mi * 16 + (lane & 15)) * FPP + akcol * 2);
                ldm_x4(ph[mi], sb + OFF_PH + ao);
                ldm_x4(pl[mi], sb + OFF_PL + ao);
            }
#pragma unroll
            for (int nj = 0; nj < 2; nj++) {
                int keyrow = kk * 16 + (lane & 15);
                int dcol   = wn * 32 + nj * 16 + (lane >> 4) * 8;
                uint32_t bo = (uint32_t)(keyrow * FQP + dcol * 2);
                ldm_x4t(vh[nj], sb + OFF_VH + bo);
                ldm_x4t(vl[nj], sb + OFF_VL + bo);
            }
#pragma unroll
            for (int mi = 0; mi < 2; mi++)
#pragma unroll
                for (int ni = 0; ni < 4; ni++) {
                    const uint32_t* bvh = &vh[ni >> 1][(ni & 1) * 2];
                    const uint32_t* bvl = &vl[ni >> 1][(ni & 1) * 2];
                    mma_bf16(oacc[mi][ni], ph[mi], bvh);
                    mma_bf16(oacc[mi][ni], ph[mi], bvl);
                    mma_bf16(oacc[mi][ni], pl[mi], bvh);
                }
        }
    }

    // ---- epilogue ----
    if (seg == 0) smL[srow] = lrun;
    __syncthreads();

#pragma unroll
    for (int mi = 0; mi < 2; mi++) {
        int rA = wm * 32 + mi * 16 + (lane >> 2);
        int rB = rA + 8;
        float iA = 1.f / smL[rA], iB = 1.f / smL[rB];
        size_t gA = ((size_t)(bb * SS + m0 + rA)) * HID + h * HD;
        size_t gB = ((size_t)(bb * SS + m0 + rB)) * HID + h * HD;
#pragma unroll
        for (int ni = 0; ni < 4; ni++) {
            int col = wn * 32 + ni * 8 + (lane & 3) * 2;
            float v0 = oacc[mi][ni][0] * iA, v1 = oacc[mi][ni][1] * iA;
            float v2 = oacc[mi][ni][2] * iB, v3 = oacc[mi][ni][3] * iB;
            __nv_bfloat16 h0 = __float2bfloat16(v0), h1 = __float2bfloat16(v1);
            __nv_bfloat16 h2 = __float2bfloat16(v2), h3 = __float2bfloat16(v3);
            *(__nv_bfloat162*)(ohi + gA + col) = __nv_bfloat162(h0, h1);
            *(__nv_bfloat162*)(ohi + gB + col) = __nv_bfloat162(h2, h3);
            *(__nv_bfloat162*)(olo + gA + col) = __nv_bfloat162(
                __float2bfloat16(v0 - __bfloat162float(h0)),
                __float2bfloat16(v1 - __bfloat162float(h1)));
            *(__nv_bfloat162*)(olo + gB + col) = __nv_bfloat162(
                __float2bfloat16(v2 - __bfloat162float(h2)),
                __float2bfloat16(v3 - __bfloat162float(h3)));
        }
    }
}

// ---------------------------------------------------------------------------
// Launch
// ---------------------------------------------------------------------------
extern "C" void kernel_launch(void* const* d_in, const int* in_sizes, int n_in,
                              void* d_out, int out_size)
{
    const float* X  = (const float*)d_in[0];
    const float* Wq = (const float*)d_in[1];
    const float* bq = (const float*)d_in[2];
    const float* Wk = (const float*)d_in[3];
    const float* bk = (const float*)d_in[4];
    const float* Wv = (const float*)d_in[5];
    const float* bv = (const float*)d_in[6];
    const float* Wo = (const float*)d_in[7];
    const float* bo = (const float*)d_in[8];
    float* out = (float*)d_out;

    __nv_bfloat16 *xh, *xl, *qh, *ql, *kh, *kl, *vh, *vl, *ah, *al;
    __nv_bfloat16 *wqh, *wql, *wkh, *wkl, *wvh, *wvl, *woh, *wol;
    cudaGetSymbolAddress((void**)&xh, g_xhi);  cudaGetSymbolAddress((void**)&xl, g_xlo);
    cudaGetSymbolAddress((void**)&qh, g_qhi);  cudaGetSymbolAddress((void**)&ql, g_qlo);
    cudaGetSymbolAddress((void**)&kh, g_khi);  cudaGetSymbolAddress((void**)&kl, g_klo);
    cudaGetSymbolAddress((void**)&vh, g_vhi);  cudaGetSymbolAddress((void**)&vl, g_vlo);
    cudaGetSymbolAddress((void**)&ah, g_ahi);  cudaGetSymbolAddress((void**)&al, g_alo);
    cudaGetSymbolAddress((void**)&wqh, g_wqh); cudaGetSymbolAddress((void**)&wql, g_wql);
    cudaGetSymbolAddress((void**)&wkh, g_wkh); cudaGetSymbolAddress((void**)&wkl, g_wkl);
    cudaGetSymbolAddress((void**)&wvh, g_wvh); cudaGetSymbolAddress((void**)&wvl, g_wvl);
    cudaGetSymbolAddress((void**)&woh, g_woh); cudaGetSymbolAddress((void**)&wol, g_wol);

    cudaFuncSetAttribute(gemm_mma_kernel,
                         cudaFuncAttributeMaxDynamicSharedMemorySize, PROJ_SMEM);
    cudaFuncSetAttribute(mqa_mma_kernel,
                         cudaFuncAttributeMaxDynamicSharedMemorySize, FLASH_SMEM);

    // 1. splits (X + weights)
    split_kernel<<<(MROWS * HID / 4 + 255) / 256, 256>>>(X, xh, xl, MROWS * HID / 4);
    split_kernel<<<(HID * HID / 4 + 255) / 256, 256>>>(Wq, wqh, wql, HID * HID / 4);
    split_kernel<<<(HID * HD / 4 + 255) / 256, 256>>>(Wk, wkh, wkl, HID * HD / 4);
    split_kernel<<<(HID * HD / 4 + 255) / 256, 256>>>(Wv, wvh, wvl, HID * HD / 4);
    split_kernel<<<(HID * HID / 4 + 255) / 256, 256>>>(Wo, woh, wol, HID * HID / 4);

    // 2. projections (bf16 hi/lo outputs, no f32 round-trip)
    gemm_mma_kernel<<<dim3(HID / 128, MROWS / 128), 256, PROJ_SMEM>>>(
        xh, xl, wqh, wql, bq, nullptr, qh, ql, HID);
    gemm_mma_kernel<<<dim3(HD / 128, MROWS / 128), 256, PROJ_SMEM>>>(
        xh, xl, wkh, wkl, bk, nullptr, kh, kl, HD);
    gemm_mma_kernel<<<dim3(HD / 128, MROWS / 128), 256, PROJ_SMEM>>>(
        xh, xl, wvh, wvl, bv, nullptr, vh, vl, HD);

    // 3. flash attention (writes attn hi/lo directly)
    mqa_mma_kernel<<<dim3(SS / 64, NH, BB), 256, FLASH_SMEM>>>(
        qh, ql, kh, kl, vh, vl, ah, al);

    // 4. output projection (f32 final)
    gemm_mma_kernel<<<dim3(HID / 128, MROWS / 128), 256, PROJ_SMEM>>>(
        ah, al, woh, wol, bo, out, nullptr, nullptr, HID);
}

// round 5
// speedup vs baseline: 4.2381x; 1.1886x over previous
#include <cuda_runtime.h>
#include <cuda_bf16.h>
#include <cstdint>
#include <math.h>

// Problem constants
#define BB   2
#define SS   2048
#define HID  2048
#define NH   16
#define HD   128
#define MROWS (BB*SS)   // 4096

// ---------------------------------------------------------------------------
// Warp-MMA primitives
// ---------------------------------------------------------------------------
__device__ __forceinline__ uint32_t smem_u32(const void* p) {
    uint32_t a;
    asm("{ .reg .u64 t; cvta.to.shared.u64 t, %1; cvt.u32.u64 %0, t; }"
        : "=r"(a) : "l"(p));
    return a;
}
__device__ __forceinline__ void ldm_x4(uint32_t* r, uint32_t addr) {
    asm volatile("ldmatrix.sync.aligned.m8n8.x4.shared.b16 {%0,%1,%2,%3}, [%4];"
        : "=r"(r[0]), "=r"(r[1]), "=r"(r[2]), "=r"(r[3]) : "r"(addr));
}
__device__ __forceinline__ void ldm_x4t(uint32_t* r, uint32_t addr) {
    asm volatile("ldmatrix.sync.aligned.m8n8.x4.trans.shared.b16 {%0,%1,%2,%3}, [%4];"
        : "=r"(r[0]), "=r"(r[1]), "=r"(r[2]), "=r"(r[3]) : "r"(addr));
}
__device__ __forceinline__ void mma_bf16(float* d, const uint32_t* a, const uint32_t* b) {
    asm volatile(
        "mma.sync.aligned.m16n8k16.row.col.f32.bf16.bf16.f32 "
        "{%0,%1,%2,%3}, {%4,%5,%6,%7}, {%8,%9}, {%0,%1,%2,%3};"
        : "+f"(d[0]), "+f"(d[1]), "+f"(d[2]), "+f"(d[3])
        : "r"(a[0]), "r"(a[1]), "r"(a[2]), "r"(a[3]), "r"(b[0]), "r"(b[1]));
}
__device__ __forceinline__ void cp16(uint32_t saddr, const void* g) {
    asm volatile("cp.async.cg.shared.global [%0], [%1], 16;"
        :: "r"(saddr), "l"(g));
}
#define CP_COMMIT() asm volatile("cp.async.commit_group;")
#define CP_WAIT(n)  asm volatile("cp.async.wait_group %0;" :: "n"(n))

__device__ __forceinline__ uint32_t pack2(__nv_bfloat16 a, __nv_bfloat16 b) {
    __nv_bfloat162 t(a, b);
    return *(uint32_t*)&t;
}

// ---------------------------------------------------------------------------
// Scratch (device globals; no allocation allowed)
// ---------------------------------------------------------------------------
__device__ __nv_bfloat16 g_xhi[MROWS * HID], g_xlo[MROWS * HID];
__device__ __nv_bfloat16 g_qhi[MROWS * HID], g_qlo[MROWS * HID];
__device__ __nv_bfloat16 g_khi[MROWS * HD],  g_klo[MROWS * HD];
__device__ __nv_bfloat16 g_vhi[MROWS * HD],  g_vlo[MROWS * HD];
__device__ __nv_bfloat16 g_ahi[MROWS * HID], g_alo[MROWS * HID];
__device__ __nv_bfloat16 g_wqh[HID * HID], g_wql[HID * HID];
__device__ __nv_bfloat16 g_woh[HID * HID], g_wol[HID * HID];
__device__ __nv_bfloat16 g_wkh[HID * HD],  g_wkl[HID * HD];
__device__ __nv_bfloat16 g_wvh[HID * HD],  g_wvl[HID * HD];

// ---------------------------------------------------------------------------
// Split fp32 -> bf16 hi + lo (with optional scale folding)
// ---------------------------------------------------------------------------
__global__ void split_kernel(const float* __restrict__ in,
                             __nv_bfloat16* __restrict__ hi,
                             __nv_bfloat16* __restrict__ lo, int n4, float sc)
{
    int i = blockIdx.x * blockDim.x + threadIdx.x;
    if (i >= n4) return;
    float4 v = ((const float4*)in)[i];
    v.x *= sc; v.y *= sc; v.z *= sc; v.w *= sc;
    __nv_bfloat16 h0 = __float2bfloat16(v.x), h1 = __float2bfloat16(v.y);
    __nv_bfloat16 h2 = __float2bfloat16(v.z), h3 = __float2bfloat16(v.w);
    ((__nv_bfloat162*)hi)[2 * i + 0] = __nv_bfloat162(h0, h1);
    ((__nv_bfloat162*)hi)[2 * i + 1] = __nv_bfloat162(h2, h3);
    ((__nv_bfloat162*)lo)[2 * i + 0] = __nv_bfloat162(
        __float2bfloat16(v.x - __bfloat162float(h0)),
        __float2bfloat16(v.y - __bfloat162float(h1)));
    ((__nv_bfloat162*)lo)[2 * i + 1] = __nv_bfloat162(
        __float2bfloat16(v.z - __bfloat162float(h2)),
        __float2bfloat16(v.w - __bfloat162float(h3)));
}

// ---------------------------------------------------------------------------
// Projection GEMM body (128x128 tile, BK=32, 8 warps, hi/lo 3-pass)
// ---------------------------------------------------------------------------
#define PA_PITCH 80
#define PB_PITCH 272
#define PA_TILE  (128 * PA_PITCH)
#define PB_TILE  (32 * PB_PITCH)
#define PSTAGE   (2 * PA_TILE + 2 * PB_TILE)
#define PROJ_SMEM (2 * PSTAGE)
#define NKC 64

__device__ __forceinline__ void gemm_body(
    const __nv_bfloat16* __restrict__ Ahi, const __nv_bfloat16* __restrict__ Alo,
    const __nv_bfloat16* __restrict__ Bhi, const __nv_bfloat16* __restrict__ Blo,
    const float* __restrict__ bias, float bsc,
    float* __restrict__ Cf, __nv_bfloat16* __restrict__ Chi,
    __nv_bfloat16* __restrict__ Clo, int Nd, char* smx)
{
    const uint32_t sb = smem_u32(smx);
    const int tid  = threadIdx.x;
    const int lane = tid & 31;
    const int wid  = tid >> 5;
    const int wm   = wid >> 2;
    const int wn   = wid & 3;
    const int n0   = blockIdx.x << 7;
    const int m0   = blockIdx.y << 7;

    const __nv_bfloat16* gA_h = Ahi + ((size_t)m0 << 11);
    const __nv_bfloat16* gA_l = Alo + ((size_t)m0 << 11);

    float acc[4][4][4];
#pragma unroll
    for (int i = 0; i < 4; i++)
#pragma unroll
        for (int j = 0; j < 4; j++)
#pragma unroll
            for (int k = 0; k < 4; k++) acc[i][j][k] = 0.f;

    auto loadA = [&](uint32_t s, const __nv_bfloat16* g) {
#pragma unroll
        for (int i = 0; i < 2; i++) {
            int q = tid + (i << 8);
            int r = q >> 2, c = q & 3;
            cp16(s + r * PA_PITCH + c * 16, g + (size_t)r * 2048 + c * 8);
        }
    };
    auto loadB = [&](uint32_t s, const __nv_bfloat16* g) {
#pragma unroll
        for (int i = 0; i < 2; i++) {
            int q = tid + (i << 8);
            int r = q >> 4, c = q & 15;
            cp16(s + r * PB_PITCH + c * 16, g + (size_t)r * Nd + c * 8);
        }
    };
    auto loadStage = [&](int buf, int ks) {
        uint32_t s = sb + buf * PSTAGE;
        loadA(s,                         gA_h + (size_t)ks * 32);
        loadA(s + PA_TILE,               gA_l + (size_t)ks * 32);
        loadB(s + 2 * PA_TILE,           Bhi + (size_t)ks * 32 * Nd + n0);
        loadB(s + 2 * PA_TILE + PB_TILE, Blo + (size_t)ks * 32 * Nd + n0);
    };

    loadStage(0, 0);
    CP_COMMIT();

    for (int ks = 0; ks < NKC; ks++) {
        if (ks + 1 < NKC) { loadStage((ks + 1) & 1, ks + 1); CP_COMMIT(); CP_WAIT(1); }
        else              { CP_WAIT(0); }
        __syncthreads();

        const uint32_t st = sb + (ks & 1) * PSTAGE;
        const uint32_t sAh = st, sAl = st + PA_TILE;
        const uint32_t sBh = st + 2 * PA_TILE, sBl = sBh + PB_TILE;

#pragma unroll
        for (int kk = 0; kk < 2; kk++) {
            uint32_t ah[4][4], al[4][4], bh[2][4], bl[2][4];
            const int akcol = kk * 16 + (lane >> 4) * 8;
#pragma unroll
            for (int mi = 0; mi < 4; mi++) {
                uint32_t ao = (uint32_t)((wm * 64 + mi * 16 + (lane & 15)) * PA_PITCH + akcol * 2);
                ldm_x4(ah[mi], sAh + ao);
                ldm_x4(al[mi], sAl + ao);
            }
            const int bkrow = kk * 16 + (lane & 15);
#pragma unroll
            for (int nj = 0; nj < 2; nj++) {
                int ncol = wn * 32 + nj * 16 + (lane >> 4) * 8;
                uint32_t bo = (uint32_t)(bkrow * PB_PITCH + ncol * 2);
                ldm_x4t(bh[nj], sBh + bo);
                ldm_x4t(bl[nj], sBl + bo);
            }
#pragma unroll
            for (int mi = 0; mi < 4; mi++)
#pragma unroll
                for (int ni = 0; ni < 4; ni++) {
                    const uint32_t* ph = &bh[ni >> 1][(ni & 1) * 2];
                    const uint32_t* pl = &bl[ni >> 1][(ni & 1) * 2];
                    mma_bf16(acc[mi][ni], ah[mi], ph);
                    mma_bf16(acc[mi][ni], ah[mi], pl);
                    mma_bf16(acc[mi][ni], al[mi], ph);
                }
        }
        __syncthreads();
    }

#pragma unroll
    for (int mi = 0; mi < 4; mi++) {
        int rA = m0 + wm * 64 + mi * 16 + (lane >> 2);
        int rB = rA + 8;
#pragma unroll
        for (int ni = 0; ni < 4; ni++) {
            int col = n0 + wn * 32 + ni * 8 + (lane & 3) * 2;
            float b0 = bias[col] * bsc, b1 = bias[col + 1] * bsc;
            float v0 = acc[mi][ni][0] + b0, v1 = acc[mi][ni][1] + b1;
            float v2 = acc[mi][ni][2] + b0, v3 = acc[mi][ni][3] + b1;
            if (Cf) {
                *(float2*)(Cf + (size_t)rA * Nd + col) = make_float2(v0, v1);
                *(float2*)(Cf + (size_t)rB * Nd + col) = make_float2(v2, v3);
            } else {
                __nv_bfloat16 h0 = __float2bfloat16(v0), h1 = __float2bfloat16(v1);
                __nv_bfloat16 h2 = __float2bfloat16(v2), h3 = __float2bfloat16(v3);
                *(__nv_bfloat162*)(Chi + (size_t)rA * Nd + col) = __nv_bfloat162(h0, h1);
                *(__nv_bfloat162*)(Chi + (size_t)rB * Nd + col) = __nv_bfloat162(h2, h3);
                *(__nv_bfloat162*)(Clo + (size_t)rA * Nd + col) = __nv_bfloat162(
                    __float2bfloat16(v0 - __bfloat162float(h0)),
                    __float2bfloat16(v1 - __bfloat162float(h1)));
                *(__nv_bfloat162*)(Clo + (size_t)rB * Nd + col) = __nv_bfloat162(
                    __float2bfloat16(v2 - __bfloat162float(h2)),
                    __float2bfloat16(v3 - __bfloat162float(h3)));
            }
        }
    }
}

__global__ __launch_bounds__(256, 1) void gemm_mma_kernel(
    const __nv_bfloat16* Ahi, const __nv_bfloat16* Alo,
    const __nv_bfloat16* Bhi, const __nv_bfloat16* Blo,
    const float* bias, float bsc,
    float* Cf, __nv_bfloat16* Chi, __nv_bfloat16* Clo, int Nd)
{
    extern __shared__ char smx[];
    gemm_body(Ahi, Alo, Bhi, Blo, bias, bsc, Cf, Chi, Clo, Nd, smx);
}

// Fused K+V projection: blockIdx.z selects operand/output set.
__global__ __launch_bounds__(256, 1) void gemm_kv_kernel(
    const __nv_bfloat16* Ahi, const __nv_bfloat16* Alo,
    const __nv_bfloat16* Bkh, const __nv_bfloat16* Bkl, const float* bk,
    __nv_bfloat16* Kh, __nv_bfloat16* Kl,
    const __nv_bfloat16* Bvh, const __nv_bfloat16* Bvl, const float* bv,
    __nv_bfloat16* Vh, __nv_bfloat16* Vl)
{
    extern __shared__ char smx[];
    if (blockIdx.z == 0)
        gemm_body(Ahi, Alo, Bkh, Bkl, bk, 1.f, nullptr, Kh, Kl, HD, smx);
    else
        gemm_body(Ahi, Alo, Bvh, Bvl, bv, 1.f, nullptr, Vh, Vl, HD, smx);
}

// ---------------------------------------------------------------------------
// Flash attention (MQA), fragment-resident softmax (FA2 style).
// CTA: 128 q-rows; 8 warps, each warp 16 rows x full key/d extent.
// KV tiles of 64 keys, double buffered. No S/P smem round trips.
// ---------------------------------------------------------------------------
#define FQP 272
#define OFF_QH 0
#define OFF_QL 34816
#define OFF_ST 69632          // stages start
#define STG    69632          // stage stride: KH,KL,VH,VL each 17408
#define FLASH_SMEM (OFF_ST + 2 * STG)   // 208896
#define NT (SS / 64)

__global__ __launch_bounds__(256, 1) void mqa_mma_kernel(
    const __nv_bfloat16* __restrict__ qhi, const __nv_bfloat16* __restrict__ qlo,
    const __nv_bfloat16* __restrict__ khi, const __nv_bfloat16* __restrict__ klo,
    const __nv_bfloat16* __restrict__ vhi, const __nv_bfloat16* __restrict__ vlo,
    __nv_bfloat16* __restrict__ ohi, __nv_bfloat16* __restrict__ olo)
{
    extern __shared__ char smx[];
    const uint32_t sb = smem_u32(smx);
    const int tid  = threadIdx.x;
    const int lane = tid & 31;
    const int wid  = tid >> 5;
    const int wr   = wid << 4;          // warp row base (0..112)
    const int m0   = blockIdx.x << 7;
    const int h    = blockIdx.y;
    const int bb   = blockIdx.z;

    auto loadQ = [&](uint32_t s, const __nv_bfloat16* g) {
#pragma unroll
        for (int i = 0; i < 8; i++) {
            int q = tid + (i << 8);
            int r = q >> 4, c = q & 15;
            cp16(s + r * FQP + c * 16, g + (size_t)r * HID + c * 8);
        }
    };
    auto loadKV64 = [&](uint32_t s, const __nv_bfloat16* g) {
#pragma unroll
        for (int i = 0; i < 4; i++) {
            int q = tid + (i << 8);
            int r = q >> 4, c = q & 15;
            cp16(s + r * FQP + c * 16, g + (size_t)r * HD + c * 8);
        }
    };
    auto loadStage = [&](int buf, int t) {
        uint32_t s = sb + OFF_ST + buf * STG;
        const size_t kvb = ((size_t)(bb * SS + t * 64)) * HD;
        loadKV64(s,             khi + kvb);
        loadKV64(s + 17408,     klo + kvb);
        loadKV64(s + 2 * 17408, vhi + kvb);
        loadKV64(s + 3 * 17408, vlo + kvb);
    };

    // prologue: Q + stage 0 (group 0), stage 1 (group 1)
    const size_t qbase = ((size_t)(bb * SS + m0)) * HID + h * HD;
    loadQ(sb + OFF_QH, qhi + qbase);
    loadQ(sb + OFF_QL, qlo + qbase);
    loadStage(0, 0);
    CP_COMMIT();
    loadStage(1, 1);
    CP_COMMIT();

    float mrunA = -INFINITY, mrunB = -INFINITY, lrunA = 0.f, lrunB = 0.f;
    float oacc[16][4];
#pragma unroll
    for (int i = 0; i < 16; i++)
#pragma unroll
        for (int k = 0; k < 4; k++) oacc[i][k] = 0.f;

    for (int t = 0; t < NT; t++) {
        if (t < NT - 2) { CP_WAIT(1); } else { CP_WAIT(0); }
        __syncthreads();

        const uint32_t st = sb + OFF_ST + (t & 1) * STG;
        const uint32_t sKh = st, sKl = st + 17408;
        const uint32_t sVh = st + 2 * 17408, sVl = st + 3 * 17408;

        // ---- S = Q @ K^T : warp tile m16 x n64 ----
        float sacc[8][4];
#pragma unroll
        for (int i = 0; i < 8; i++)
#pragma unroll
            for (int k = 0; k < 4; k++) sacc[i][k] = 0.f;

#pragma unroll
        for (int kk = 0; kk < 8; kk++) {
            uint32_t qh4[4], ql4[4];
            uint32_t qo = (uint32_t)((wr + (lane & 15)) * FQP + (kk * 16 + (lane >> 4) * 8) * 2);
            ldm_x4(qh4, sb + OFF_QH + qo);
            ldm_x4(ql4, sb + OFF_QL + qo);
            const int kcol = kk * 16 + ((lane >> 3) & 1) * 8;
#pragma unroll
            for (int nj = 0; nj < 4; nj++) {
                uint32_t kh4[4], kl4[4];
                int keyrow = nj * 16 + (lane >> 4) * 8 + (lane & 7);
                uint32_t ko = (uint32_t)(keyrow * FQP + kcol * 2);
                ldm_x4(kh4, sKh + ko);
                ldm_x4(kl4, sKl + ko);
                mma_bf16(sacc[2 * nj],     qh4, &kh4[0]);
                mma_bf16(sacc[2 * nj],     qh4, &kl4[0]);
                mma_bf16(sacc[2 * nj],     ql4, &kh4[0]);
                mma_bf16(sacc[2 * nj + 1], qh4, &kh4[2]);
                mma_bf16(sacc[2 * nj + 1], qh4, &kl4[2]);
                mma_bf16(sacc[2 * nj + 1], ql4, &kh4[2]);
            }
        }

        // ---- fragment-resident online softmax ----
        float mA = -INFINITY, mB = -INFINITY;
#pragma unroll
        for (int nt = 0; nt < 8; nt++) {
            mA = fmaxf(mA, fmaxf(sacc[nt][0], sacc[nt][1]));
            mB = fmaxf(mB, fmaxf(sacc[nt][2], sacc[nt][3]));
        }
        mA = fmaxf(mA, __shfl_xor_sync(0xffffffffu, mA, 1));
        mA = fmaxf(mA, __shfl_xor_sync(0xffffffffu, mA, 2));
        mB = fmaxf(mB, __shfl_xor_sync(0xffffffffu, mB, 1));
        mB = fmaxf(mB, __shfl_xor_sync(0xffffffffu, mB, 2));

        float mnewA = fmaxf(mrunA, mA), mnewB = fmaxf(mrunB, mB);
        float alphaA = __expf(mrunA - mnewA), alphaB = __expf(mrunB - mnewB);
        mrunA = mnewA; mrunB = mnewB;

        uint32_t pfh[4][4], pfl[4][4];
        float sumA = 0.f, sumB = 0.f;
#pragma unroll
        for (int nt = 0; nt < 8; nt++) {
            float p0 = __expf(sacc[nt][0] - mnewA);
            float p1 = __expf(sacc[nt][1] - mnewA);
            float p2 = __expf(sacc[nt][2] - mnewB);
            float p3 = __expf(sacc[nt][3] - mnewB);
            sumA += p0 + p1; sumB += p2 + p3;
            __nv_bfloat16 h0 = __float2bfloat16(p0), h1 = __float2bfloat16(p1);
            __nv_bfloat16 h2 = __float2bfloat16(p2), h3 = __float2bfloat16(p3);
            int kk2 = nt >> 1, sl = (nt & 1) * 2;
            pfh[kk2][sl]     = pack2(h0, h1);
            pfh[kk2][sl + 1] = pack2(h2, h3);
            pfl[kk2][sl]     = pack2(__float2bfloat16(p0 - __bfloat162float(h0)),
                                     __float2bfloat16(p1 - __bfloat162float(h1)));
            pfl[kk2][sl + 1] = pack2(__float2bfloat16(p2 - __bfloat162float(h2)),
                                     __float2bfloat16(p3 - __bfloat162float(h3)));
        }
        sumA += __shfl_xor_sync(0xffffffffu, sumA, 1);
        sumA += __shfl_xor_sync(0xffffffffu, sumA, 2);
        sumB += __shfl_xor_sync(0xffffffffu, sumB, 1);
        sumB += __shfl_xor_sync(0xffffffffu, sumB, 2);
        lrunA = lrunA * alphaA + sumA;
        lrunB = lrunB * alphaB + sumB;

#pragma unroll
        for (int nt = 0; nt < 16; nt++) {
            oacc[nt][0] *= alphaA; oacc[nt][1] *= alphaA;
            oacc[nt][2] *= alphaB; oacc[nt][3] *= alphaB;
        }

        // ---- O += P @ V : warp tile m16 x d128, keys 64 ----
#pragma unroll
        for (int kk2 = 0; kk2 < 4; kk2++) {
            const int keyrow = kk2 * 16 + (lane & 15);
#pragma unroll
            for (int dj = 0; dj < 8; dj++) {
                uint32_t vh4[4], vl4[4];
                int dcol = dj * 16 + (lane >> 4) * 8;
                uint32_t vo = (uint32_t)(keyrow * FQP + dcol * 2);
                ldm_x4t(vh4, sVh + vo);
                ldm_x4t(vl4, sVl + vo);
                mma_bf16(oacc[2 * dj],     pfh[kk2], &vh4[0]);
                mma_bf16(oacc[2 * dj],     pfh[kk2], &vl4[0]);
                mma_bf16(oacc[2 * dj],     pfl[kk2], &vh4[0]);
                mma_bf16(oacc[2 * dj + 1], pfh[kk2], &vh4[2]);
                mma_bf16(oacc[2 * dj + 1], pfh[kk2], &vl4[2]);
                mma_bf16(oacc[2 * dj + 1], pfl[kk2], &vh4[2]);
            }
        }

        __syncthreads();   // all warps done reading buf (t&1)
        if (t + 2 < NT) { loadStage(t & 1, t + 2); CP_COMMIT(); }
    }

    // ---- epilogue ----
    const float invA = 1.f / lrunA, invB = 1.f / lrunB;
    int rA = wr + (lane >> 2), rB = rA + 8;
    size_t gA = ((size_t)(bb * SS + m0 + rA)) * HID + h * HD;
    size_t gB = ((size_t)(bb * SS + m0 + rB)) * HID + h * HD;
#pragma unroll
    for (int nt = 0; nt < 16; nt++) {
        int col = nt * 8 + (lane & 3) * 2;
        float v0 = oacc[nt][0] * invA, v1 = oacc[nt][1] * invA;
        float v2 = oacc[nt][2] * invB, v3 = oacc[nt][3] * invB;
        __nv_bfloat16 h0 = __float2bfloat16(v0), h1 = __float2bfloat16(v1);
        __nv_bfloat16 h2 = __float2bfloat16(v2), h3 = __float2bfloat16(v3);
        *(__nv_bfloat162*)(ohi + gA + col) = __nv_bfloat162(h0, h1);
        *(__nv_bfloat162*)(ohi + gB + col) = __nv_bfloat162(h2, h3);
        *(__nv_bfloat162*)(olo + gA + col) = __nv_bfloat162(
            __float2bfloat16(v0 - __bfloat162float(h0)),
            __float2bfloat16(v1 - __bfloat162float(h1)));
        *(__nv_bfloat162*)(olo + gB + col) = __nv_bfloat162(
            __float2bfloat16(v2 - __bfloat162float(h2)),
            __float2bfloat16(v3 - __bfloat162float(h3)));
    }
}

// ---------------------------------------------------------------------------
// Launch
// ---------------------------------------------------------------------------
extern "C" void kernel_launch(void* const* d_in, const int* in_sizes, int n_in,
                              void* d_out, int out_size)
{
    const float* X  = (const float*)d_in[0];
    const float* Wq = (const float*)d_in[1];
    const float* bq = (const float*)d_in[2];
    const float* Wk = (const float*)d_in[3];
    const float* bk = (const float*)d_in[4];
    const float* Wv = (const float*)d_in[5];
    const float* bv = (const float*)d_in[6];
    const float* Wo = (const float*)d_in[7];
    const float* bo = (const float*)d_in[8];
    float* out = (float*)d_out;

    const float qscale = 0.088388347648318447f;   // 1/sqrt(128)

    __nv_bfloat16 *xh, *xl, *qh, *ql, *kh, *kl, *vh, *vl, *ah, *al;
    __nv_bfloat16 *wqh, *wql, *wkh, *wkl, *wvh, *wvl, *woh, *wol;
    cudaGetSymbolAddress((void**)&xh, g_xhi);  cudaGetSymbolAddress((void**)&xl, g_xlo);
    cudaGetSymbolAddress((void**)&qh, g_qhi);  cudaGetSymbolAddress((void**)&ql, g_qlo);
    cudaGetSymbolAddress((void**)&kh, g_khi);  cudaGetSymbolAddress((void**)&kl, g_klo);
    cudaGetSymbolAddress((void**)&vh, g_vhi);  cudaGetSymbolAddress((void**)&vl, g_vlo);
    cudaGetSymbolAddress((void**)&ah, g_ahi);  cudaGetSymbolAddress((void**)&al, g_alo);
    cudaGetSymbolAddress((void**)&wqh, g_wqh); cudaGetSymbolAddress((void**)&wql, g_wql);
    cudaGetSymbolAddress((void**)&wkh, g_wkh); cudaGetSymbolAddress((void**)&wkl, g_wkl);
    cudaGetSymbolAddress((void**)&wvh, g_wvh); cudaGetSymbolAddress((void**)&wvl, g_wvl);
    cudaGetSymbolAddress((void**)&woh, g_woh); cudaGetSymbolAddress((void**)&wol, g_wol);

    cudaFuncSetAttribute(gemm_mma_kernel,
                         cudaFuncAttributeMaxDynamicSharedMemorySize, PROJ_SMEM);
    cudaFuncSetAttribute(gemm_kv_kernel,
                         cudaFuncAttributeMaxDynamicSharedMemorySize, PROJ_SMEM);
    cudaFuncSetAttribute(mqa_mma_kernel,
                         cudaFuncAttributeMaxDynamicSharedMemorySize, FLASH_SMEM);

    // 1. splits (scale folded into Wq)
    split_kernel<<<(MROWS * HID / 4 + 255) / 256, 256>>>(X, xh, xl, MROWS * HID / 4, 1.f);
    split_kernel<<<(HID * HID / 4 + 255) / 256, 256>>>(Wq, wqh, wql, HID * HID / 4, qscale);
    split_kernel<<<(HID * HD / 4 + 255) / 256, 256>>>(Wk, wkh, wkl, HID * HD / 4, 1.f);
    split_kernel<<<(HID * HD / 4 + 255) / 256, 256>>>(Wv, wvh, wvl, HID * HD / 4, 1.f);
    split_kernel<<<(HID * HID / 4 + 255) / 256, 256>>>(Wo, woh, wol, HID * HID / 4, 1.f);

    // 2. Q projection (scaled), fused K+V projection
    gemm_mma_kernel<<<dim3(HID / 128, MROWS / 128), 256, PROJ_SMEM>>>(
        xh, xl, wqh, wql, bq, qscale, nullptr, qh, ql, HID);
    gemm_kv_kernel<<<dim3(1, MROWS / 128, 2), 256, PROJ_SMEM>>>(
        xh, xl, wkh, wkl, bk, kh, kl, wvh, wvl, bv, vh, vl);

    // 3. flash attention
    mqa_mma_kernel<<<dim3(SS / 128, NH, BB), 256, FLASH_SMEM>>>(
        qh, ql, kh, kl, vh, vl, ah, al);

    // 4. output projection
    gemm_mma_kernel<<<dim3(HID / 128, MROWS / 128), 256, PROJ_SMEM>>>(
        ah, al, woh, wol, bo, 1.f, out, nullptr, nullptr, HID);
}

// round 7
// speedup vs baseline: 4.5712x; 1.0786x over previous
#include <cuda_runtime.h>
#include <cuda_bf16.h>
#include <cstdint>
#include <math.h>

// Problem constants
#define BB   2
#define SS   2048
#define HID  2048
#define NH   16
#define HD   128
#define MROWS (BB*SS)   // 4096

// ---------------------------------------------------------------------------
// Warp-MMA primitives
// ---------------------------------------------------------------------------
__device__ __forceinline__ uint32_t smem_u32(const void* p) {
    uint32_t a;
    asm("{ .reg .u64 t; cvta.to.shared.u64 t, %1; cvt.u32.u64 %0, t; }"
        : "=r"(a) : "l"(p));
    return a;
}
__device__ __forceinline__ void ldm_x4(uint32_t* r, uint32_t addr) {
    asm volatile("ldmatrix.sync.aligned.m8n8.x4.shared.b16 {%0,%1,%2,%3}, [%4];"
        : "=r"(r[0]), "=r"(r[1]), "=r"(r[2]), "=r"(r[3]) : "r"(addr));
}
__device__ __forceinline__ void ldm_x4t(uint32_t* r, uint32_t addr) {
    asm volatile("ldmatrix.sync.aligned.m8n8.x4.trans.shared.b16 {%0,%1,%2,%3}, [%4];"
        : "=r"(r[0]), "=r"(r[1]), "=r"(r[2]), "=r"(r[3]) : "r"(addr));
}
__device__ __forceinline__ void mma_bf16(float* d, const uint32_t* a, const uint32_t* b) {
    asm volatile(
        "mma.sync.aligned.m16n8k16.row.col.f32.bf16.bf16.f32 "
        "{%0,%1,%2,%3}, {%4,%5,%6,%7}, {%8,%9}, {%0,%1,%2,%3};"
        : "+f"(d[0]), "+f"(d[1]), "+f"(d[2]), "+f"(d[3])
        : "r"(a[0]), "r"(a[1]), "r"(a[2]), "r"(a[3]), "r"(b[0]), "r"(b[1]));
}
__device__ __forceinline__ void cp16(uint32_t saddr, const void* g) {
    asm volatile("cp.async.cg.shared.global [%0], [%1], 16;"
        :: "r"(saddr), "l"(g));
}
#define CP_COMMIT() asm volatile("cp.async.commit_group;")
#define CP_WAIT(n)  asm volatile("cp.async.wait_group %0;" :: "n"(n))

__device__ __forceinline__ uint32_t pack2(__nv_bfloat16 a, __nv_bfloat16 b) {
    __nv_bfloat162 t(a, b);
    return *(uint32_t*)&t;
}

// ---------------------------------------------------------------------------
// Scratch (device globals; no allocation allowed)
// ---------------------------------------------------------------------------
__device__ __nv_bfloat16 g_xhi[MROWS * HID], g_xlo[MROWS * HID];
__device__ __nv_bfloat16 g_qhi[MROWS * HID], g_qlo[MROWS * HID];
__device__ __nv_bfloat16 g_khi[MROWS * HD],  g_klo[MROWS * HD];
__device__ __nv_bfloat16 g_vhi[MROWS * HD],  g_vlo[MROWS * HD];
__device__ __nv_bfloat16 g_ahi[MROWS * HID], g_alo[MROWS * HID];
__device__ __nv_bfloat16 g_wqh[HID * HID], g_wql[HID * HID];
__device__ __nv_bfloat16 g_woh[HID * HID], g_wol[HID * HID];
__device__ __nv_bfloat16 g_wkh[HID * HD],  g_wkl[HID * HD];
__device__ __nv_bfloat16 g_wvh[HID * HD],  g_wvl[HID * HD];

// ---------------------------------------------------------------------------
// Combined split: one launch covers X, Wq(scaled), Wo, Wk, Wv.
// Segment sizes in float4 blocks of 256 threads:
//   X: 8192 blk | Wq: 4096 | Wo: 4096 | Wk: 256 | Wv: 256   -> 16896 blocks
// ---------------------------------------------------------------------------
#define SPLIT_BLOCKS 16896

__global__ void split_all_kernel(
    const float* __restrict__ X,  const float* __restrict__ Wq,
    const float* __restrict__ Wk, const float* __restrict__ Wv,
    const float* __restrict__ Wo,
    __nv_bfloat16* xh, __nv_bfloat16* xl,
    __nv_bfloat16* wqh, __nv_bfloat16* wql,
    __nv_bfloat16* wkh, __nv_bfloat16* wkl,
    __nv_bfloat16* wvh, __nv_bfloat16* wvl,
    __nv_bfloat16* woh, __nv_bfloat16* wol, float qscale)
{
    int b = blockIdx.x;
    const float* in; __nv_bfloat16 *hi, *lo; int base; float sc = 1.f;
    if (b < 8192)       { in = X;  hi = xh;  lo = xl;  base = b; }
    else if (b < 12288) { in = Wq; hi = wqh; lo = wql; base = b - 8192; sc = qscale; }
    else if (b < 16384) { in = Wo; hi = woh; lo = wol; base = b - 12288; }
    else if (b < 16640) { in = Wk; hi = wkh; lo = wkl; base = b - 16384; }
    else                { in = Wv; hi = wvh; lo = wvl; base = b - 16640; }

    int i = base * 256 + threadIdx.x;
    float4 v = ((const float4*)in)[i];
    v.x *= sc; v.y *= sc; v.z *= sc; v.w *= sc;
    __nv_bfloat16 h0 = __float2bfloat16(v.x), h1 = __float2bfloat16(v.y);
    __nv_bfloat16 h2 = __float2bfloat16(v.z), h3 = __float2bfloat16(v.w);
    ((__nv_bfloat162*)hi)[2 * i + 0] = __nv_bfloat162(h0, h1);
    ((__nv_bfloat162*)hi)[2 * i + 1] = __nv_bfloat162(h2, h3);
    ((__nv_bfloat162*)lo)[2 * i + 0] = __nv_bfloat162(
        __float2bfloat16(v.x - __bfloat162float(h0)),
        __float2bfloat16(v.y - __bfloat162float(h1)));
    ((__nv_bfloat162*)lo)[2 * i + 1] = __nv_bfloat162(
        __float2bfloat16(v.z - __bfloat162float(h2)),
        __float2bfloat16(v.w - __bfloat162float(h3)));
}

// ---------------------------------------------------------------------------
// Projection GEMM body (128x128 tile, BK=32, 8 warps, hi/lo 3-pass)
// 3-stage cp.async pipeline; 2 CTAs/SM.
// ---------------------------------------------------------------------------
#define PA_PITCH 80
#define PB_PITCH 272
#define PA_TILE  (128 * PA_PITCH)
#define PB_TILE  (32 * PB_PITCH)
#define PSTAGE   (2 * PA_TILE + 2 * PB_TILE)   // 37888
#define PROJ_SMEM (3 * PSTAGE)                 // 113664
#define NKC 64

__device__ __forceinline__ void gemm_body(
    const __nv_bfloat16* __restrict__ Ahi, const __nv_bfloat16* __restrict__ Alo,
    const __nv_bfloat16* __restrict__ Bhi, const __nv_bfloat16* __restrict__ Blo,
    const float* __restrict__ bias, float bsc,
    float* __restrict__ Cf, __nv_bfloat16* __restrict__ Chi,
    __nv_bfloat16* __restrict__ Clo, int Nd, char* smx)
{
    const uint32_t sb = smem_u32(smx);
    const int tid  = threadIdx.x;
    const int lane = tid & 31;
    const int wid  = tid >> 5;
    const int wm   = wid >> 2;
    const int wn   = wid & 3;
    const int n0   = blockIdx.x << 7;
    const int m0   = blockIdx.y << 7;

    const __nv_bfloat16* gA_h = Ahi + ((size_t)m0 << 11);
    const __nv_bfloat16* gA_l = Alo + ((size_t)m0 << 11);

    float acc[4][4][4];
#pragma unroll
    for (int i = 0; i < 4; i++)
#pragma unroll
        for (int j = 0; j < 4; j++)
#pragma unroll
            for (int k = 0; k < 4; k++) acc[i][j][k] = 0.f;

    auto loadA = [&](uint32_t s, const __nv_bfloat16* g) {
#pragma unroll
        for (int i = 0; i < 2; i++) {
            int q = tid + (i << 8);
            int r = q >> 2, c = q & 3;
            cp16(s + r * PA_PITCH + c * 16, g + (size_t)r * 2048 + c * 8);
        }
    };
    auto loadB = [&](uint32_t s, const __nv_bfloat16* g) {
#pragma unroll
        for (int i = 0; i < 2; i++) {
            int q = tid + (i << 8);
            int r = q >> 4, c = q & 15;
            cp16(s + r * PB_PITCH + c * 16, g + (size_t)r * Nd + c * 8);
        }
    };
    auto loadStage = [&](int buf, int ks) {
        uint32_t s = sb + buf * PSTAGE;
        loadA(s,                         gA_h + (size_t)ks * 32);
        loadA(s + PA_TILE,               gA_l + (size_t)ks * 32);
        loadB(s + 2 * PA_TILE,           Bhi + (size_t)ks * 32 * Nd + n0);
        loadB(s + 2 * PA_TILE + PB_TILE, Blo + (size_t)ks * 32 * Nd + n0);
    };

    loadStage(0, 0); CP_COMMIT();
    loadStage(1, 1); CP_COMMIT();

    int buf = 0, nbuf = 2;
    for (int ks = 0; ks < NKC; ks++) {
        __syncthreads();   // stage buffer `nbuf` free for reuse
        if (ks + 2 < NKC) {
            loadStage(nbuf, ks + 2); CP_COMMIT(); CP_WAIT(2);
        } else if (ks + 1 < NKC) { CP_WAIT(1); }
        else                     { CP_WAIT(0); }
        __syncthreads();

        const uint32_t st = sb + buf * PSTAGE;
        const uint32_t sAh = st, sAl = st + PA_TILE;
        const uint32_t sBh = st + 2 * PA_TILE, sBl = sBh + PB_TILE;

#pragma unroll
        for (int kk = 0; kk < 2; kk++) {
            uint32_t ah[4][4], al[4][4], bh[2][4], bl[2][4];
            const int akcol = kk * 16 + (lane >> 4) * 8;
#pragma unroll
            for (int mi = 0; mi < 4; mi++) {
                uint32_t ao = (uint32_t)((wm * 64 + mi * 16 + (lane & 15)) * PA_PITCH + akcol * 2);
                ldm_x4(ah[mi], sAh + ao);
                ldm_x4(al[mi], sAl + ao);
            }
            const int bkrow = kk * 16 + (lane & 15);
#pragma unroll
            for (int nj = 0; nj < 2; nj++) {
                int ncol = wn * 32 + nj * 16 + (lane >> 4) * 8;
                uint32_t bo = (uint32_t)(bkrow * PB_PITCH + ncol * 2);
                ldm_x4t(bh[nj], sBh + bo);
                ldm_x4t(bl[nj], sBl + bo);
            }
#pragma unroll
            for (int mi = 0; mi < 4; mi++)
#pragma unroll
                for (int ni = 0; ni < 4; ni++) {
                    const uint32_t* ph = &bh[ni >> 1][(ni & 1) * 2];
                    const uint32_t* pl = &bl[ni >> 1][(ni & 1) * 2];
                    mma_bf16(acc[mi][ni], ah[mi], ph);
                    mma_bf16(acc[mi][ni], ah[mi], pl);
                    mma_bf16(acc[mi][ni], al[mi], ph);
                }
        }
        buf  = (buf == 2) ? 0 : buf + 1;
        nbuf = (nbuf == 2) ? 0 : nbuf + 1;
    }

#pragma unroll
    for (int mi = 0; mi < 4; mi++) {
        int rA = m0 + wm * 64 + mi * 16 + (lane >> 2);
        int rB = rA + 8;
#pragma unroll
        for (int ni = 0; ni < 4; ni++) {
            int col = n0 + wn * 32 + ni * 8 + (lane & 3) * 2;
            float b0 = bias[col] * bsc, b1 = bias[col + 1] * bsc;
            float v0 = acc[mi][ni][0] + b0, v1 = acc[mi][ni][1] + b1;
            float v2 = acc[mi][ni][2] + b0, v3 = acc[mi][ni][3] + b1;
            if (Cf) {
                *(float2*)(Cf + (size_t)rA * Nd + col) = make_float2(v0, v1);
                *(float2*)(Cf + (size_t)rB * Nd + col) = make_float2(v2, v3);
            } else {
                __nv_bfloat16 h0 = __float2bfloat16(v0), h1 = __float2bfloat16(v1);
                __nv_bfloat16 h2 = __float2bfloat16(v2), h3 = __float2bfloat16(v3);
                *(__nv_bfloat162*)(Chi + (size_t)rA * Nd + col) = __nv_bfloat162(h0, h1);
                *(__nv_bfloat162*)(Chi + (size_t)rB * Nd + col) = __nv_bfloat162(h2, h3);
                *(__nv_bfloat162*)(Clo + (size_t)rA * Nd + col) = __nv_bfloat162(
                    __float2bfloat16(v0 - __bfloat162float(h0)),
                    __float2bfloat16(v1 - __bfloat162float(h1)));
                *(__nv_bfloat162*)(Clo + (size_t)rB * Nd + col) = __nv_bfloat162(
                    __float2bfloat16(v2 - __bfloat162float(h2)),
                    __float2bfloat16(v3 - __bfloat162float(h3)));
            }
        }
    }
}

__global__ __launch_bounds__(256, 2) void gemm_mma_kernel(
    const __nv_bfloat16* Ahi, const __nv_bfloat16* Alo,
    const __nv_bfloat16* Bhi, const __nv_bfloat16* Blo,
    const float* bias, float bsc,
    float* Cf, __nv_bfloat16* Chi, __nv_bfloat16* Clo, int Nd)
{
    extern __shared__ char smx[];
    gemm_body(Ahi, Alo, Bhi, Blo, bias, bsc, Cf, Chi, Clo, Nd, smx);
}

// Fused K+V projection: blockIdx.z selects operand/output set.
__global__ __launch_bounds__(256, 2) void gemm_kv_kernel(
    const __nv_bfloat16* Ahi, const __nv_bfloat16* Alo,
    const __nv_bfloat16* Bkh, const __nv_bfloat16* Bkl, const float* bk,
    __nv_bfloat16* Kh, __nv_bfloat16* Kl,
    const __nv_bfloat16* Bvh, const __nv_bfloat16* Bvl, const float* bv,
    __nv_bfloat16* Vh, __nv_bfloat16* Vl)
{
    extern __shared__ char smx[];
    if (blockIdx.z == 0)
        gemm_body(Ahi, Alo, Bkh, Bkl, bk, 1.f, nullptr, Kh, Kl, HD, smx);
    else
        gemm_body(Ahi, Alo, Bvh, Bvl, bv, 1.f, nullptr, Vh, Vl, HD, smx);
}

// ---------------------------------------------------------------------------
// Flash attention (MQA), fragment-resident softmax (FA2 style).
// CTA: 128 q-rows; 8 warps, each warp 16 rows x full key/d extent.
// KV tiles of 64 keys, double buffered.
// ---------------------------------------------------------------------------
#define FQP 272
#define OFF_QH 0
#define OFF_QL 34816
#define OFF_ST 69632
#define STG    69632
#define FLASH_SMEM (OFF_ST + 2 * STG)   // 208896
#define NT (SS / 64)

__global__ __launch_bounds__(256, 1) void mqa_mma_kernel(
    const __nv_bfloat16* __restrict__ qhi, const __nv_bfloat16* __restrict__ qlo,
    const __nv_bfloat16* __restrict__ khi, const __nv_bfloat16* __restrict__ klo,
    const __nv_bfloat16* __restrict__ vhi, const __nv_bfloat16* __restrict__ vlo,
    __nv_bfloat16* __restrict__ ohi, __nv_bfloat16* __restrict__ olo)
{
    extern __shared__ char smx[];
    const uint32_t sb = smem_u32(smx);
    const int tid  = threadIdx.x;
    const int lane = tid & 31;
    const int wid  = tid >> 5;
    const int wr   = wid << 4;
    const int m0   = blockIdx.x << 7;
    const int h    = blockIdx.y;
    const int bb   = blockIdx.z;

    auto loadQ = [&](uint32_t s, const __nv_bfloat16* g) {
#pragma unroll
        for (int i = 0; i < 8; i++) {
            int q = tid + (i << 8);
            int r = q >> 4, c = q & 15;
            cp16(s + r * FQP + c * 16, g + (size_t)r * HID + c * 8);
        }
    };
    auto loadKV64 = [&](uint32_t s, const __nv_bfloat16* g) {
#pragma unroll
        for (int i = 0; i < 4; i++) {
            int q = tid + (i << 8);
            int r = q >> 4, c = q & 15;
            cp16(s + r * FQP + c * 16, g + (size_t)r * HD + c * 8);
        }
    };
    auto loadStage = [&](int buf, int t) {
        uint32_t s = sb + OFF_ST + buf * STG;
        const size_t kvb = ((size_t)(bb * SS + t * 64)) * HD;
        loadKV64(s,             khi + kvb);
        loadKV64(s + 17408,     klo + kvb);
        loadKV64(s + 2 * 17408, vhi + kvb);
        loadKV64(s + 3 * 17408, vlo + kvb);
    };

    const size_t qbase = ((size_t)(bb * SS + m0)) * HID + h * HD;
    loadQ(sb + OFF_QH, qhi + qbase);
    loadQ(sb + OFF_QL, qlo + qbase);
    loadStage(0, 0);
    CP_COMMIT();
    loadStage(1, 1);
    CP_COMMIT();

    float mrunA = -INFINITY, mrunB = -INFINITY, lrunA = 0.f, lrunB = 0.f;
    float oacc[16][4];
#pragma unroll
    for (int i = 0; i < 16; i++)
#pragma unroll
        for (int k = 0; k < 4; k++) oacc[i][k] = 0.f;

    for (int t = 0; t < NT; t++) {
        if (t < NT - 2) { CP_WAIT(1); } else { CP_WAIT(0); }
        __syncthreads();

        const uint32_t st = sb + OFF_ST + (t & 1) * STG;
        const uint32_t sKh = st, sKl = st + 17408;
        const uint32_t sVh = st + 2 * 17408, sVl = st + 3 * 17408;

        float sacc[8][4];
#pragma unroll
        for (int i = 0; i < 8; i++)
#pragma unroll
            for (int k = 0; k < 4; k++) sacc[i][k] = 0.f;

#pragma unroll
        for (int kk = 0; kk < 8; kk++) {
            uint32_t qh4[4], ql4[4];
            uint32_t qo = (uint32_t)((wr + (lane & 15)) * FQP + (kk * 16 + (lane >> 4) * 8) * 2);
            ldm_x4(qh4, sb + OFF_QH + qo);
            ldm_x4(ql4, sb + OFF_QL + qo);
            const int kcol = kk * 16 + ((lane >> 3) & 1) * 8;
#pragma unroll
            for (int nj = 0; nj < 4; nj++) {
                uint32_t kh4[4], kl4[4];
                int keyrow = nj * 16 + (lane >> 4) * 8 + (lane & 7);
                uint32_t ko = (uint32_t)(keyrow * FQP + kcol * 2);
                ldm_x4(kh4, sKh + ko);
                ldm_x4(kl4, sKl + ko);
                mma_bf16(sacc[2 * nj],     qh4, &kh4[0]);
                mma_bf16(sacc[2 * nj],     qh4, &kl4[0]);
                mma_bf16(sacc[2 * nj],     ql4, &kh4[0]);
                mma_bf16(sacc[2 * nj + 1], qh4, &kh4[2]);
                mma_bf16(sacc[2 * nj + 1], qh4, &kl4[2]);
                mma_bf16(sacc[2 * nj + 1], ql4, &kh4[2]);
            }
        }

        float mA = -INFINITY, mB = -INFINITY;
#pragma unroll
        for (int nt = 0; nt < 8; nt++) {
            mA = fmaxf(mA, fmaxf(sacc[nt][0], sacc[nt][1]));
            mB = fmaxf(mB, fmaxf(sacc[nt][2], sacc[nt][3]));
        }
        mA = fmaxf(mA, __shfl_xor_sync(0xffffffffu, mA, 1));
        mA = fmaxf(mA, __shfl_xor_sync(0xffffffffu, mA, 2));
        mB = fmaxf(mB, __shfl_xor_sync(0xffffffffu, mB, 1));
        mB = fmaxf(mB, __shfl_xor_sync(0xffffffffu, mB, 2));

        float mnewA = fmaxf(mrunA, mA), mnewB = fmaxf(mrunB, mB);
        float alphaA = __expf(mrunA - mnewA), alphaB = __expf(mrunB - mnewB);
        mrunA = mnewA; mrunB = mnewB;

        uint32_t pfh[4][4], pfl[4][4];
        float sumA = 0.f, sumB = 0.f;
#pragma unroll
        for (int nt = 0; nt < 8; nt++) {
            float p0 = __expf(sacc[nt][0] - mnewA);
            float p1 = __expf(sacc[nt][1] - mnewA);
            float p2 = __expf(sacc[nt][2] - mnewB);
            float p3 = __expf(sacc[nt][3] - mnewB);
            sumA += p0 + p1; sumB += p2 + p3;
            __nv_bfloat16 h0 = __float2bfloat16(p0), h1 = __float2bfloat16(p1);
            __nv_bfloat16 h2 = __float2bfloat16(p2), h3 = __float2bfloat16(p3);
            int kk2 = nt >> 1, sl = (nt & 1) * 2;
            pfh[kk2][sl]     = pack2(h0, h1);
            pfh[kk2][sl + 1] = pack2(h2, h3);
            pfl[kk2][sl]     = pack2(__float2bfloat16(p0 - __bfloat162float(h0)),
                                     __float2bfloat16(p1 - __bfloat162float(h1)));
            pfl[kk2][sl + 1] = pack2(__float2bfloat16(p2 - __bfloat162float(h2)),
                                     __float2bfloat16(p3 - __bfloat162float(h3)));
        }
        sumA += __shfl_xor_sync(0xffffffffu, sumA, 1);
        sumA += __shfl_xor_sync(0xffffffffu, sumA, 2);
        sumB += __shfl_xor_sync(0xffffffffu, sumB, 1);
        sumB += __shfl_xor_sync(0xffffffffu, sumB, 2);
        lrunA = lrunA * alphaA + sumA;
        lrunB = lrunB * alphaB + sumB;

#pragma unroll
        for (int nt = 0; nt < 16; nt++) {
            oacc[nt][0] *= alphaA; oacc[nt][1] *= alphaA;
            oacc[nt][2] *= alphaB; oacc[nt][3] *= alphaB;
        }

#pragma unroll
        for (int kk2 = 0; kk2 < 4; kk2++) {
            const int keyrow = kk2 * 16 + (lane & 15);
#pragma unroll
            for (int dj = 0; dj < 8; dj++) {
                uint32_t vh4[4], vl4[4];
                int dcol = dj * 16 + (lane >> 4) * 8;
                uint32_t vo = (uint32_t)(keyrow * FQP + dcol * 2);
                ldm_x4t(vh4, sVh + vo);
                ldm_x4t(vl4, sVl + vo);
                mma_bf16(oacc[2 * dj],     pfh[kk2], &vh4[0]);
                mma_bf16(oacc[2 * dj],     pfh[kk2], &vl4[0]);
                mma_bf16(oacc[2 * dj],     pfl[kk2], &vh4[0]);
                mma_bf16(oacc[2 * dj + 1], pfh[kk2], &vh4[2]);
                mma_bf16(oacc[2 * dj + 1], pfh[kk2], &vl4[2]);
                mma_bf16(oacc[2 * dj + 1], pfl[kk2], &vh4[2]);
            }
        }

        __syncthreads();
        if (t + 2 < NT) { loadStage(t & 1, t + 2); CP_COMMIT(); }
    }

    const float invA = 1.f / lrunA, invB = 1.f / lrunB;
    int rA = wr + (lane >> 2), rB = rA + 8;
    size_t gA = ((size_t)(bb * SS + m0 + rA)) * HID + h * HD;
    size_t gB = ((size_t)(bb * SS + m0 + rB)) * HID + h * HD;
#pragma unroll
    for (int nt = 0; nt < 16; nt++) {
        int col = nt * 8 + (lane & 3) * 2;
        float v0 = oacc[nt][0] * invA, v1 = oacc[nt][1] * invA;
        float v2 = oacc[nt][2] * invB, v3 = oacc[nt][3] * invB;
        __nv_bfloat16 h0 = __float2bfloat16(v0), h1 = __float2bfloat16(v1);
        __nv_bfloat16 h2 = __float2bfloat16(v2), h3 = __float2bfloat16(v3);
        *(__nv_bfloat162*)(ohi + gA + col) = __nv_bfloat162(h0, h1);
        *(__nv_bfloat162*)(ohi + gB + col) = __nv_bfloat162(h2, h3);
        *(__nv_bfloat162*)(olo + gA + col) = __nv_bfloat162(
            __float2bfloat16(v0 - __bfloat162float(h0)),
            __float2bfloat16(v1 - __bfloat162float(h1)));
        *(__nv_bfloat162*)(olo + gB + col) = __nv_bfloat162(
            __float2bfloat16(v2 - __bfloat162float(h2)),
            __float2bfloat16(v3 - __bfloat162float(h3)));
    }
}

// ---------------------------------------------------------------------------
// Launch
// ---------------------------------------------------------------------------
extern "C" void kernel_launch(void* const* d_in, const int* in_sizes, int n_in,
                              void* d_out, int out_size)
{
    const float* X  = (const float*)d_in[0];
    const float* Wq = (const float*)d_in[1];
    const float* bq = (const float*)d_in[2];
    const float* Wk = (const float*)d_in[3];
    const float* bk = (const float*)d_in[4];
    const float* Wv = (const float*)d_in[5];
    const float* bv = (const float*)d_in[6];
    const float* Wo = (const float*)d_in[7];
    const float* bo = (const float*)d_in[8];
    float* out = (float*)d_out;

    const float qscale = 0.088388347648318447f;   // 1/sqrt(128)

    __nv_bfloat16 *xh, *xl, *qh, *ql, *kh, *kl, *vh, *vl, *ah, *al;
    __nv_bfloat16 *wqh, *wql, *wkh, *wkl, *wvh, *wvl, *woh, *wol;
    cudaGetSymbolAddress((void**)&xh, g_xhi);  cudaGetSymbolAddress((void**)&xl, g_xlo);
    cudaGetSymbolAddress((void**)&qh, g_qhi);  cudaGetSymbolAddress((void**)&ql, g_qlo);
    cudaGetSymbolAddress((void**)&kh, g_khi);  cudaGetSymbolAddress((void**)&kl, g_klo);
    cudaGetSymbolAddress((void**)&vh, g_vhi);  cudaGetSymbolAddress((void**)&vl, g_vlo);
    cudaGetSymbolAddress((void**)&ah, g_ahi);  cudaGetSymbolAddress((void**)&al, g_alo);
    cudaGetSymbolAddress((void**)&wqh, g_wqh); cudaGetSymbolAddress((void**)&wql, g_wql);
    cudaGetSymbolAddress((void**)&wkh, g_wkh); cudaGetSymbolAddress((void**)&wkl, g_wkl);
    cudaGetSymbolAddress((void**)&wvh, g_wvh); cudaGetSymbolAddress((void**)&wvl, g_wvl);
    cudaGetSymbolAddress((void**)&woh, g_woh); cudaGetSymbolAddress((void**)&wol, g_wol);

    cudaFuncSetAttribute(gemm_mma_kernel,
                         cudaFuncAttributeMaxDynamicSharedMemorySize, PROJ_SMEM);
    cudaFuncSetAttribute(gemm_kv_kernel,
                         cudaFuncAttributeMaxDynamicSharedMemorySize, PROJ_SMEM);
    cudaFuncSetAttribute(mqa_mma_kernel,
                         cudaFuncAttributeMaxDynamicSharedMemorySize, FLASH_SMEM);

    // 1. all splits in one launch (scale folded into Wq)
    split_all_kernel<<<SPLIT_BLOCKS, 256>>>(
        X, Wq, Wk, Wv, Wo,
        xh, xl, wqh, wql, wkh, wkl, wvh, wvl, woh, wol, qscale);

    // 2. Q projection (scaled), fused K+V projection
    gemm_mma_kernel<<<dim3(HID / 128, MROWS / 128), 256, PROJ_SMEM>>>(
        xh, xl, wqh, wql, bq, qscale, nullptr, qh, ql, HID);
    gemm_kv_kernel<<<dim3(1, MROWS / 128, 2), 256, PROJ_SMEM>>>(
        xh, xl, wkh, wkl, bk, kh, kl, wvh, wvl, bv, vh, vl);

    // 3. flash attention
    mqa_mma_kernel<<<dim3(SS / 128, NH, BB), 256, FLASH_SMEM>>>(
        qh, ql, kh, kl, vh, vl, ah, al);

    // 4. output projection
    gemm_mma_kernel<<<dim3(HID / 128, MROWS / 128), 256, PROJ_SMEM>>>(
        ah, al, woh, wol, bo, 1.f, out, nullptr, nullptr, HID);
}